// round 3
// baseline (speedup 1.0000x reference)
#include <cuda_runtime.h>
#include <cstdint>
#include <cstddef>

// Problem-size upper bounds (actual sizes derived from in_sizes at launch).
#define NN 100000
#define EE 1600000
#define TT (EE + NN)

// ---------------- scratch (static device globals; no allocation) ----------------
__device__ float g_h[(size_t)NN * 96];      // h (layer1), then h (layer2)
__device__ float g_out[(size_t)NN * 96];    // aggregation output per layer
__device__ float g_small[(size_t)NN * 32];  // h2in, then t (pre-lin1)
__device__ float g_es[NN];
__device__ float g_ed[NN];
__device__ int   g_deg[NN];
__device__ int   g_rowptr[NN + 1];
__device__ int   g_cursor[NN];
__device__ int   g_csr[TT];
__device__ int   g_bsum[1024];
__device__ int   g_is64;

// ---------------- edge-index dtype probe ----------------
// If edge_index was transported as int64, every odd 32-bit word is the high
// half of a small nonnegative value -> 0. If int32, odd words are random node
// ids; 256 consecutive zeros is impossible for this input. Deterministic.
__global__ void k_probe(const int* __restrict__ ei32) {
    if (threadIdx.x == 0 && blockIdx.x == 0) {
        int acc = 0;
        #pragma unroll 8
        for (int i = 1; i < 512; i += 2) acc |= ei32[i];
        g_is64 = (acc == 0) ? 1 : 0;
    }
}

__device__ __forceinline__ int load_idx(const void* ei, size_t i, int is64, int N) {
    int v = is64 ? (int)((const long long*)ei)[i] : ((const int*)ei)[i];
    // clamp: structurally prevents OOB even under a wrong decode
    v = v < 0 ? 0 : v;
    return v >= N ? N - 1 : v;
}

// ---------------- CSR construction ----------------
__global__ void k_init_deg(int N) {
    int i = blockIdx.x * blockDim.x + threadIdx.x;
    if (i < N) g_deg[i] = 1;  // self-loop
}

__global__ void k_count(const void* __restrict__ ei, int E, int N) {
    int i = blockIdx.x * blockDim.x + threadIdx.x;
    if (i < E) {
        int d = load_idx(ei, (size_t)E + i, g_is64, N);
        atomicAdd(&g_deg[d], 1);
    }
}

// Block-local exclusive scan (blockDim must be 1024)
__global__ void k_scan_blocks(int N) {
    __shared__ int ws[32];
    int i = blockIdx.x * 1024 + threadIdx.x;
    int v = (i < N) ? g_deg[i] : 0;
    int x = v;
    int lane = threadIdx.x & 31, wid = threadIdx.x >> 5;
    #pragma unroll
    for (int o = 1; o < 32; o <<= 1) {
        int y = __shfl_up_sync(0xffffffffu, x, o);
        if (lane >= o) x += y;
    }
    if (lane == 31) ws[wid] = x;
    __syncthreads();
    if (wid == 0) {
        int w = ws[lane];
        #pragma unroll
        for (int o = 1; o < 32; o <<= 1) {
            int y = __shfl_up_sync(0xffffffffu, w, o);
            if (lane >= o) w += y;
        }
        ws[lane] = w;
    }
    __syncthreads();
    int excl = x - v + (wid ? ws[wid - 1] : 0);
    if (i < N) g_rowptr[i] = excl;
    if (threadIdx.x == 1023) g_bsum[blockIdx.x] = ws[31];
}

// Exclusive scan of block sums (blockDim must be 1024, G <= 1024)
__global__ void k_scan_sums(int G, int N) {
    __shared__ int ws[32];
    int tid = threadIdx.x;
    int v = (tid < G) ? g_bsum[tid] : 0;
    int x = v;
    int lane = tid & 31, wid = tid >> 5;
    #pragma unroll
    for (int o = 1; o < 32; o <<= 1) {
        int y = __shfl_up_sync(0xffffffffu, x, o);
        if (lane >= o) x += y;
    }
    if (lane == 31) ws[wid] = x;
    __syncthreads();
    if (wid == 0) {
        int w = ws[lane];
        #pragma unroll
        for (int o = 1; o < 32; o <<= 1) {
            int y = __shfl_up_sync(0xffffffffu, w, o);
            if (lane >= o) w += y;
        }
        ws[lane] = w;
    }
    __syncthreads();
    int excl = x - v + (wid ? ws[wid - 1] : 0);
    if (tid < G) g_bsum[tid] = excl;
    if (tid == 1023) g_rowptr[N] = ws[31];  // total edges incl self loops
}

__global__ void k_scan_add(int N) {
    int i = blockIdx.x * blockDim.x + threadIdx.x;
    if (i < N) {
        int v = g_rowptr[i] + g_bsum[i >> 10];
        g_rowptr[i] = v;
        g_cursor[i] = v;
    }
}

__global__ void k_fill(const void* __restrict__ ei, int E, int N) {
    int i = blockIdx.x * blockDim.x + threadIdx.x;
    int tot = E + N;
    if (i >= tot) return;
    int s, d;
    if (i < E) {
        int is64 = g_is64;
        s = load_idx(ei, i, is64, N);
        d = load_idx(ei, (size_t)E + i, is64, N);
    } else {
        s = i - E;
        d = s;
    }
    int pos = atomicAdd(&g_cursor[d], 1);
    if (pos < TT) g_csr[pos] = s;
}

// ---------------- GEMM: C[N,96] = A[N,K] @ W[K,96] ----------------
template <int K>
__global__ void k_gemm96(const float* __restrict__ A, const float* __restrict__ W,
                         float* __restrict__ C, int N) {
    __shared__ float As[64][K + 4];
    int tid = threadIdx.x;
    int tn = tid & 15;   // column group: cols tn + 16*j, j<6
    int tm = tid >> 4;   // row group: rows tm*4 + i, i<4
    int row0 = blockIdx.x * 64;

    constexpr int V = K / 4;  // float4 per row
    for (int i = tid; i < 64 * V; i += 256) {
        int r = i / V, c4 = i % V;
        float4 v = make_float4(0.f, 0.f, 0.f, 0.f);
        if (row0 + r < N)
            v = __ldg(reinterpret_cast<const float4*>(A + (size_t)(row0 + r) * K) + c4);
        *reinterpret_cast<float4*>(&As[r][c4 * 4]) = v;
    }
    __syncthreads();

    float acc[4][6];
    #pragma unroll
    for (int i = 0; i < 4; ++i)
        #pragma unroll
        for (int j = 0; j < 6; ++j) acc[i][j] = 0.f;

    #pragma unroll 4
    for (int k = 0; k < K; ++k) {
        float a0 = As[tm * 4 + 0][k];
        float a1 = As[tm * 4 + 1][k];
        float a2 = As[tm * 4 + 2][k];
        float a3 = As[tm * 4 + 3][k];
        #pragma unroll
        for (int j = 0; j < 6; ++j) {
            float w = __ldg(&W[k * 96 + tn + 16 * j]);
            acc[0][j] = fmaf(a0, w, acc[0][j]);
            acc[1][j] = fmaf(a1, w, acc[1][j]);
            acc[2][j] = fmaf(a2, w, acc[2][j]);
            acc[3][j] = fmaf(a3, w, acc[3][j]);
        }
    }
    #pragma unroll
    for (int i = 0; i < 4; ++i) {
        int r = row0 + tm * 4 + i;
        if (r < N) {
            #pragma unroll
            for (int j = 0; j < 6; ++j) C[(size_t)r * 96 + tn + 16 * j] = acc[i][j];
        }
    }
}

// ---------------- attention scores: es = h@a_s, ed = h@a_d ----------------
__global__ void k_scores(const float* __restrict__ h, const float* __restrict__ as_,
                         const float* __restrict__ ad_, int N) {
    int gw = (blockIdx.x * blockDim.x + threadIdx.x) >> 5;
    if (gw >= N) return;
    int lane = threadIdx.x & 31;
    const float* hr = h + (size_t)gw * 96;
    float s = 0.f, d = 0.f;
    #pragma unroll
    for (int f = 0; f < 3; ++f) {
        float hv = hr[lane + 32 * f];
        s = fmaf(hv, __ldg(&as_[lane + 32 * f]), s);
        d = fmaf(hv, __ldg(&ad_[lane + 32 * f]), d);
    }
    #pragma unroll
    for (int o = 16; o; o >>= 1) {
        s += __shfl_xor_sync(0xffffffffu, s, o);
        d += __shfl_xor_sync(0xffffffffu, d, o);
    }
    if (lane == 0) { g_es[gw] = s; g_ed[gw] = d; }
}

// ---------------- warp-per-node softmax aggregation ----------------
__global__ void k_agg(const float* __restrict__ h, const float* __restrict__ bias,
                      float* __restrict__ outp, int N) {
    int gw = (blockIdx.x * blockDim.x + threadIdx.x) >> 5;
    if (gw >= N) return;
    int lane = threadIdx.x & 31;
    int beg = g_rowptr[gw], end = g_rowptr[gw + 1];
    float edn = g_ed[gw];

    // pass 1: segment max (matches reference softmax stabilization)
    float mloc = -INFINITY;
    for (int j = beg + lane; j < end; j += 32) {
        int s = __ldg(&g_csr[j]);
        float e = __ldg(&g_es[s]) + edn;
        e = (e > 0.f) ? e : 0.2f * e;
        mloc = fmaxf(mloc, e);
    }
    #pragma unroll
    for (int o = 16; o; o >>= 1) mloc = fmaxf(mloc, __shfl_xor_sync(0xffffffffu, mloc, o));
    float m = mloc;

    // pass 2: p = exp(e-m); accumulate sum(p) and sum(p * h[src])
    float acc0 = 0.f, acc1 = 0.f, acc2 = 0.f, psum = 0.f;
    for (int j0 = beg; j0 < end; j0 += 32) {
        int j = j0 + lane;
        int cnt = min(32, end - j0);
        int s = 0;
        float p = 0.f;
        if (j < end) {
            s = __ldg(&g_csr[j]);
            float e = __ldg(&g_es[s]) + edn;
            e = (e > 0.f) ? e : 0.2f * e;
            p = __expf(e - m);
        }
        psum += p;
        #pragma unroll 8
        for (int k = 0; k < cnt; ++k) {
            float pk = __shfl_sync(0xffffffffu, p, k);
            int sk = __shfl_sync(0xffffffffu, s, k);
            const float* hs = h + (size_t)sk * 96;
            acc0 = fmaf(pk, __ldg(hs + lane), acc0);
            acc1 = fmaf(pk, __ldg(hs + lane + 32), acc1);
            acc2 = fmaf(pk, __ldg(hs + lane + 64), acc2);
        }
    }
    #pragma unroll
    for (int o = 16; o; o >>= 1) psum += __shfl_xor_sync(0xffffffffu, psum, o);

    float degf = (float)(end - beg);
    float scale = (1.f / fmaxf(psum, 1e-16f)) * (1.f / fmaxf(degf, 1.f));
    size_t base = (size_t)gw * 96;
    outp[base + lane]      = fmaf(acc0, scale, __ldg(&bias[lane]));
    outp[base + lane + 32] = fmaf(acc1, scale, __ldg(&bias[lane + 32]));
    outp[base + lane + 64] = fmaf(acc2, scale, __ldg(&bias[lane + 64]));
}

// ---------------- reshape(3,N,-1).sum(0) == sum of three contiguous thirds ----------------
template <bool RELU>
__global__ void k_thirds(const float* __restrict__ f, float* __restrict__ o, int n4) {
    // n4 = N*32/4 float4 elements per third
    int i = blockIdx.x * blockDim.x + threadIdx.x;
    if (i >= n4) return;
    const float4* f4 = reinterpret_cast<const float4*>(f);
    float4 a = f4[i], b = f4[i + n4], c = f4[i + 2 * n4];
    float4 r;
    r.x = a.x + b.x + c.x;
    r.y = a.y + b.y + c.y;
    r.z = a.z + b.z + c.z;
    r.w = a.w + b.w + c.w;
    if (RELU) {
        r.x = fmaxf(r.x, 0.f); r.y = fmaxf(r.y, 0.f);
        r.z = fmaxf(r.z, 0.f); r.w = fmaxf(r.w, 0.f);
    }
    reinterpret_cast<float4*>(o)[i] = r;
}

// ---------------- fused lin1 -> relu -> lin2 -> sigmoid ----------------
__global__ void k_final(const float* __restrict__ t, const float* __restrict__ Wl1,
                        const float* __restrict__ bl1, const float* __restrict__ Wl2,
                        const float* __restrict__ bl2, float* __restrict__ out, int N) {
    __shared__ float w1s[32 * 96];
    __shared__ float w2s[96 * 32];
    __shared__ float b1s[96];
    __shared__ float b2s[32];
    __shared__ float zs[8][96];
    for (int i = threadIdx.x; i < 3072; i += blockDim.x) {
        w1s[i] = Wl1[i];
        w2s[i] = Wl2[i];
    }
    if (threadIdx.x < 96) b1s[threadIdx.x] = bl1[threadIdx.x];
    if (threadIdx.x < 32) b2s[threadIdx.x] = bl2[threadIdx.x];
    __syncthreads();

    int lane = threadIdx.x & 31;
    int wib = threadIdx.x >> 5;
    int gw = blockIdx.x * 8 + wib;
    int stride = gridDim.x * 8;
    float* zr = zs[wib];

    for (int n = gw; n < N; n += stride) {
        float tv = t[(size_t)n * 32 + lane];
        float z0 = b1s[lane], z1 = b1s[lane + 32], z2 = b1s[lane + 64];
        #pragma unroll
        for (int j = 0; j < 32; ++j) {
            float tj = __shfl_sync(0xffffffffu, tv, j);
            z0 = fmaf(tj, w1s[j * 96 + lane], z0);
            z1 = fmaf(tj, w1s[j * 96 + lane + 32], z1);
            z2 = fmaf(tj, w1s[j * 96 + lane + 64], z2);
        }
        zr[lane] = fmaxf(z0, 0.f);
        zr[lane + 32] = fmaxf(z1, 0.f);
        zr[lane + 64] = fmaxf(z2, 0.f);
        __syncwarp();
        float y = b2s[lane];
        #pragma unroll 8
        for (int c = 0; c < 96; ++c) y = fmaf(zr[c], w2s[c * 32 + lane], y);
        out[(size_t)n * 32 + lane] = 1.f / (1.f + __expf(-y));
        __syncwarp();
    }
}

// ---------------- launch ----------------
extern "C" void kernel_launch(void* const* d_in, const int* in_sizes, int n_in,
                              void* d_out, int out_size) {
    const float* x        = (const float*)d_in[0];
    const void*  ei       = d_in[1];
    const float* W1       = (const float*)d_in[2];
    const float* as1      = (const float*)d_in[3];
    const float* ad1      = (const float*)d_in[4];
    const float* b1       = (const float*)d_in[5];
    const float* W2       = (const float*)d_in[6];
    const float* as2      = (const float*)d_in[7];
    const float* ad2      = (const float*)d_in[8];
    const float* b2       = (const float*)d_in[9];
    const float* Wl1      = (const float*)d_in[12];
    const float* bl1      = (const float*)d_in[13];
    const float* Wl2      = (const float*)d_in[14];
    const float* bl2      = (const float*)d_in[15];
    float* out = (float*)d_out;

    int N = in_sizes[0] / 128;
    int E = in_sizes[1] / 2;

    float *p_h, *p_out, *p_small;
    cudaGetSymbolAddress((void**)&p_h, g_h);
    cudaGetSymbolAddress((void**)&p_out, g_out);
    cudaGetSymbolAddress((void**)&p_small, g_small);

    int warpsBlocks = (N * 32 + 255) / 256;   // warp-per-node kernels
    int G = (N + 1023) / 1024;

    // --- edge-index dtype probe + CSR build ---
    k_probe<<<1, 32>>>((const int*)ei);
    k_init_deg<<<(N + 255) / 256, 256>>>(N);
    k_count<<<(E + 255) / 256, 256>>>(ei, E, N);
    k_scan_blocks<<<G, 1024>>>(N);
    k_scan_sums<<<1, 1024>>>(G, N);
    k_scan_add<<<(N + 255) / 256, 256>>>(N);
    k_fill<<<(E + N + 255) / 256, 256>>>(ei, E, N);

    // --- layer 1 ---
    k_gemm96<128><<<(N + 63) / 64, 256>>>(x, W1, p_h, N);
    k_scores<<<warpsBlocks, 256>>>(p_h, as1, ad1, N);
    k_agg<<<warpsBlocks, 256>>>(p_h, b1, p_out, N);
    k_thirds<true><<<(N * 8 + 255) / 256, 256>>>(p_out, p_small, N * 8);

    // --- layer 2 ---
    k_gemm96<32><<<(N + 63) / 64, 256>>>(p_small, W2, p_h, N);
    k_scores<<<warpsBlocks, 256>>>(p_h, as2, ad2, N);
    k_agg<<<warpsBlocks, 256>>>(p_h, b2, p_out, N);
    k_thirds<false><<<(N * 8 + 255) / 256, 256>>>(p_out, p_small, N * 8);

    // --- fused MLP tail ---
    k_final<<<1184, 256>>>(p_small, Wl1, bl1, Wl2, bl2, out, N);
}